// round 3
// baseline (speedup 1.0000x reference)
#include <cuda_runtime.h>
#include <cstdint>
#include <cstddef>

// ---------------- problem constants ----------------
#define T_TOK   4096
#define HID     7168
#define NH      128
#define DNOPE   128
#define DROPE   64
#define QLORA   1536
#define KVLORA  512
#define DQK     192                 // DNOPE + DROPE
#define FUSEDN  2112                // QLORA + KVLORA + DROPE

// output layout (concat of q_pe, k_pe, q_nope_out, k_nope, all f32)
#define OUT_QPE    0
#define OUT_KPE    33554432LL       // T*H*64
#define OUT_QNOPE  33816576LL       // + T*64
#define OUT_KNOPE  302252032LL      // + T*H*512

// ---------------- device scratch (no allocations allowed) ----------------
__device__ float g_fused[(size_t)T_TOK * FUSEDN];          // 34.6 MB
__device__ float g_qln  [(size_t)T_TOK * QLORA];           // 25 MB
__device__ float g_qnope[(size_t)T_TOK * NH * DNOPE];      // 268 MB
__device__ float g_cos  [T_TOK * 32];
__device__ float g_sin  [T_TOK * 32];

// ---------------- helpers ----------------
__device__ __forceinline__ unsigned f2tf(float x) {
    unsigned r; asm("cvt.rna.tf32.f32 %0, %1;" : "=r"(r) : "f"(x)); return r;
}

__device__ __forceinline__ float* sel_ptr(int sel, const float* ext) {
    switch (sel) {
        case 1: return g_fused;
        case 2: return g_qln;
        case 3: return g_qnope;
        default: return (float*)ext;
    }
}

// ---------------- tf32 GEMM (double-buffered smem) ----------------
// C[M,N] = A[M,K] (row-major, lda) * B[K,N] (row-major, ldb)
// MODE 0: plain store to C (ldc).
// MODE 1: GEMM2 epilogue. Warp tiles are 64 cols wide; head h's rope region
//   [192h+128, 192h+192) is exactly one warp tile (192h+128 = 64*(3h+2)), so
//   a warp tile is either all-nope -> g_qnope, or all-rope -> rope applied
//   in-register (partners acc[..][ni] / acc[..][ni+4]) and stored to Cext
//   (= out + OUT_QPE).
#define BM 128
#define BN 128
#define BK 16
#define SA_LD 20    // pad: conflict-free a-frag LDS
#define SB_LD 132   // pad: natural [k][n] layout

template<int MODE>
__global__ __launch_bounds__(256)
void gemm_tf32(const float* __restrict__ Aext, int selA,
               const float* __restrict__ B,
               float* __restrict__ Cext, int selC,
               int M, int N, int K, int lda, int ldb, int ldc,
               long long bsA, long long bsB, long long bsC)
{
    __shared__ unsigned sA[2][BM][SA_LD];
    __shared__ unsigned sB[2][BK][SB_LD];

    const float* A = sel_ptr(selA, Aext);
    float*       C = sel_ptr(selC, Cext);
    A += (size_t)blockIdx.z * bsA;
    B += (size_t)blockIdx.z * bsB;
    C += (size_t)blockIdx.z * bsC;

    // grouped rasterization for L2 reuse
    const int tiles_n = (N + BN - 1) / BN;
    const int tiles_m = M / BM;
    const int GRP = 8;
    int pid   = blockIdx.x;
    int nig   = GRP * tiles_n;
    int gid   = pid / nig;
    int fm    = gid * GRP;
    int gsz   = min(GRP, tiles_m - fm);
    int tm    = fm + (pid % gsz);
    int tn    = (pid % nig) / gsz;
    int m0 = tm * BM, n0 = tn * BN;

    int tid  = threadIdx.x;
    int lane = tid & 31;
    int warp = tid >> 5;
    int wm   = warp & 3;        // 4 warps along M (32 rows each)
    int wn   = warp >> 2;       // 2 warps along N (64 cols each)
    int grp  = lane >> 2;       // 0..7
    int tig  = lane & 3;        // 0..3

    // per-thread global-load coordinates (fixed across K-tiles)
    int a_row0 = tid >> 2;
    int a_kc   = (tid & 3) << 2;
    int a_row1 = (tid + 256) >> 2;
    int b_kr0  = tid >> 5;
    int b_nc   = (tid & 31) << 2;
    int b_kr1  = (tid + 256) >> 5;
    bool bok   = (n0 + b_nc) < N;

    float acc[2][8][4];
    #pragma unroll
    for (int a = 0; a < 2; a++)
        #pragma unroll
        for (int b = 0; b < 8; b++)
            #pragma unroll
            for (int c = 0; c < 4; c++) acc[a][b][c] = 0.f;

    // ---- prologue: fetch K-tile 0, stage into smem buffer 0 ----
    float4 ra0, ra1, rb0, rb1;
    ra0 = *(const float4*)(A + (size_t)(m0 + a_row0) * lda + a_kc);
    ra1 = *(const float4*)(A + (size_t)(m0 + a_row1) * lda + a_kc);
    rb0 = make_float4(0.f, 0.f, 0.f, 0.f);
    rb1 = make_float4(0.f, 0.f, 0.f, 0.f);
    if (bok) {
        rb0 = *(const float4*)(B + (size_t)b_kr0 * ldb + n0 + b_nc);
        rb1 = *(const float4*)(B + (size_t)b_kr1 * ldb + n0 + b_nc);
    }
    sA[0][a_row0][a_kc + 0] = f2tf(ra0.x);
    sA[0][a_row0][a_kc + 1] = f2tf(ra0.y);
    sA[0][a_row0][a_kc + 2] = f2tf(ra0.z);
    sA[0][a_row0][a_kc + 3] = f2tf(ra0.w);
    sA[0][a_row1][a_kc + 0] = f2tf(ra1.x);
    sA[0][a_row1][a_kc + 1] = f2tf(ra1.y);
    sA[0][a_row1][a_kc + 2] = f2tf(ra1.z);
    sA[0][a_row1][a_kc + 3] = f2tf(ra1.w);
    sB[0][b_kr0][b_nc + 0] = f2tf(rb0.x);
    sB[0][b_kr0][b_nc + 1] = f2tf(rb0.y);
    sB[0][b_kr0][b_nc + 2] = f2tf(rb0.z);
    sB[0][b_kr0][b_nc + 3] = f2tf(rb0.w);
    sB[0][b_kr1][b_nc + 0] = f2tf(rb1.x);
    sB[0][b_kr1][b_nc + 1] = f2tf(rb1.y);
    sB[0][b_kr1][b_nc + 2] = f2tf(rb1.z);
    sB[0][b_kr1][b_nc + 3] = f2tf(rb1.w);
    __syncthreads();

    const int nk = K / BK;
    for (int it = 0; it < nk; it++) {
        int cur  = it & 1;
        int nxt  = cur ^ 1;
        int kn   = (it + 1) * BK;
        bool more = kn < K;

        // prefetch next K-tile into registers (overlaps MMA below)
        if (more) {
            ra0 = *(const float4*)(A + (size_t)(m0 + a_row0) * lda + kn + a_kc);
            ra1 = *(const float4*)(A + (size_t)(m0 + a_row1) * lda + kn + a_kc);
            if (bok) {
                rb0 = *(const float4*)(B + (size_t)(kn + b_kr0) * ldb + n0 + b_nc);
                rb1 = *(const float4*)(B + (size_t)(kn + b_kr1) * ldb + n0 + b_nc);
            }
        }

        // MMA on current buffer
        #pragma unroll
        for (int ks = 0; ks < BK; ks += 8) {
            unsigned af[2][4], bf[8][2];
            #pragma unroll
            for (int mi = 0; mi < 2; mi++) {
                int r = wm * 32 + mi * 16 + grp;
                af[mi][0] = sA[cur][r    ][ks + tig];
                af[mi][1] = sA[cur][r + 8][ks + tig];
                af[mi][2] = sA[cur][r    ][ks + tig + 4];
                af[mi][3] = sA[cur][r + 8][ks + tig + 4];
            }
            #pragma unroll
            for (int ni = 0; ni < 8; ni++) {
                int c = wn * 64 + ni * 8 + grp;
                bf[ni][0] = sB[cur][ks + tig    ][c];
                bf[ni][1] = sB[cur][ks + tig + 4][c];
            }
            #pragma unroll
            for (int mi = 0; mi < 2; mi++)
                #pragma unroll
                for (int ni = 0; ni < 8; ni++) {
                    asm volatile(
                        "mma.sync.aligned.m16n8k8.row.col.f32.tf32.tf32.f32 "
                        "{%0,%1,%2,%3}, {%4,%5,%6,%7}, {%8,%9}, {%0,%1,%2,%3};"
                        : "+f"(acc[mi][ni][0]), "+f"(acc[mi][ni][1]),
                          "+f"(acc[mi][ni][2]), "+f"(acc[mi][ni][3])
                        : "r"(af[mi][0]), "r"(af[mi][1]),
                          "r"(af[mi][2]), "r"(af[mi][3]),
                          "r"(bf[ni][0]), "r"(bf[ni][1]));
                }
        }

        // stage next tile into the other buffer (safe: that buffer's readers
        // finished before the barrier that ended the previous iteration)
        if (more) {
            sA[nxt][a_row0][a_kc + 0] = f2tf(ra0.x);
            sA[nxt][a_row0][a_kc + 1] = f2tf(ra0.y);
            sA[nxt][a_row0][a_kc + 2] = f2tf(ra0.z);
            sA[nxt][a_row0][a_kc + 3] = f2tf(ra0.w);
            sA[nxt][a_row1][a_kc + 0] = f2tf(ra1.x);
            sA[nxt][a_row1][a_kc + 1] = f2tf(ra1.y);
            sA[nxt][a_row1][a_kc + 2] = f2tf(ra1.z);
            sA[nxt][a_row1][a_kc + 3] = f2tf(ra1.w);
            sB[nxt][b_kr0][b_nc + 0] = f2tf(rb0.x);
            sB[nxt][b_kr0][b_nc + 1] = f2tf(rb0.y);
            sB[nxt][b_kr0][b_nc + 2] = f2tf(rb0.z);
            sB[nxt][b_kr0][b_nc + 3] = f2tf(rb0.w);
            sB[nxt][b_kr1][b_nc + 0] = f2tf(rb1.x);
            sB[nxt][b_kr1][b_nc + 1] = f2tf(rb1.y);
            sB[nxt][b_kr1][b_nc + 2] = f2tf(rb1.z);
            sB[nxt][b_kr1][b_nc + 3] = f2tf(rb1.w);
        }
        __syncthreads();
    }

    // ---------------- epilogue ----------------
    if (MODE == 0) {
        #pragma unroll
        for (int mi = 0; mi < 2; mi++)
            #pragma unroll
            for (int half = 0; half < 2; half++) {
                int row = m0 + wm * 32 + mi * 16 + grp + half * 8;
                #pragma unroll
                for (int ni = 0; ni < 8; ni++) {
                    int col = n0 + wn * 64 + ni * 8 + 2 * tig;
                    if (col >= N) continue;
                    *(float2*)(C + (size_t)row * ldc + col)
                        = make_float2(acc[mi][ni][half * 2 + 0],
                                      acc[mi][ni][half * 2 + 1]);
                }
            }
    } else {
        int wbase   = n0 + wn * 64;              // warp-tile column base
        bool isrope = ((wbase >> 6) % 3) == 2;   // 64-col block idx mod 3
        if (!isrope) {
            #pragma unroll
            for (int mi = 0; mi < 2; mi++)
                #pragma unroll
                for (int half = 0; half < 2; half++) {
                    int row = m0 + wm * 32 + mi * 16 + grp + half * 8;
                    #pragma unroll
                    for (int ni = 0; ni < 8; ni++) {
                        int col  = wbase + ni * 8 + 2 * tig;
                        int head = col / DQK;
                        int w    = col - head * DQK;     // < 128 guaranteed
                        *(float2*)(g_qnope + (size_t)row * (NH * DNOPE)
                                   + head * DNOPE + w)
                            = make_float2(acc[mi][ni][half * 2 + 0],
                                          acc[mi][ni][half * 2 + 1]);
                    }
                }
        } else {
            int head = wbase / DQK;              // whole warp tile = one head's rope
            #pragma unroll
            for (int mi = 0; mi < 2; mi++)
                #pragma unroll
                for (int half = 0; half < 2; half++) {
                    int row = m0 + wm * 32 + mi * 16 + grp + half * 8;  // token t
                    float* ob = C + (size_t)row * (NH * DROPE) + head * DROPE;
                    const float* cp = g_cos + row * 32;
                    const float* sp = g_sin + row * 32;
                    #pragma unroll
                    for (int ni = 0; ni < 4; ni++) {
                        int j  = ni * 8 + 2 * tig;       // 0..30 (pairs j, j+1)
                        float a0 = acc[mi][ni    ][half * 2 + 0];
                        float a1 = acc[mi][ni    ][half * 2 + 1];
                        float b0 = acc[mi][ni + 4][half * 2 + 0];
                        float b1 = acc[mi][ni + 4][half * 2 + 1];
                        float c0 = cp[j], c1 = cp[j + 1];
                        float s0 = sp[j], s1 = sp[j + 1];
                        *(float2*)(ob + j)      = make_float2(a0 * c0 - b0 * s0,
                                                              a1 * c1 - b1 * s1);
                        *(float2*)(ob + 32 + j) = make_float2(b0 * c0 + a0 * s0,
                                                              b1 * c1 + a1 * s1);
                    }
                }
        }
    }
}

// ---------------- rope table (fp64 trig once per (t, j)) ----------------
__global__ void rope_table_kernel(const int* __restrict__ pos) {
    int idx = blockIdx.x * blockDim.x + threadIdx.x;
    if (idx >= T_TOK * 32) return;
    int t = idx >> 5, j = idx & 31;
    double inv = exp(-(double)j * (9.210340371976184 / 32.0));  // ln(1e4)/32
    double ang = (double)pos[t] * inv;
    g_cos[idx] = (float)cos(ang);
    g_sin[idx] = (float)sin(ang);
}

// ---------------- per-token: both RMSNorms + k_pe rope ----------------
__global__ __launch_bounds__(512)
void rms_split_kernel(const float* __restrict__ qlnw,
                      const float* __restrict__ kvlnw,
                      float* __restrict__ out)
{
    int t = blockIdx.x;
    const float* f = g_fused + (size_t)t * FUSEDN;
    int tid = threadIdx.x;
    __shared__ float red[16];
    __shared__ float sc[2];

    float x0 = f[tid], x1 = f[tid + 512], x2 = f[tid + 1024];
    float s = x0 * x0 + x1 * x1 + x2 * x2;
    #pragma unroll
    for (int o = 16; o; o >>= 1) s += __shfl_xor_sync(0xffffffffu, s, o);
    if ((tid & 31) == 0) red[tid >> 5] = s;
    __syncthreads();
    if (tid < 32) {
        float v = (tid < 16) ? red[tid] : 0.f;
        #pragma unroll
        for (int o = 8; o; o >>= 1) v += __shfl_xor_sync(0xffffffffu, v, o);
        if (tid == 0) sc[0] = rsqrtf(v / (float)QLORA + 1e-6f);
    }
    __syncthreads();

    float y  = f[1536 + tid];
    float s2 = y * y;
    #pragma unroll
    for (int o = 16; o; o >>= 1) s2 += __shfl_xor_sync(0xffffffffu, s2, o);
    if ((tid & 31) == 0) red[tid >> 5] = s2;
    __syncthreads();
    if (tid < 32) {
        float v = (tid < 16) ? red[tid] : 0.f;
        #pragma unroll
        for (int o = 8; o; o >>= 1) v += __shfl_xor_sync(0xffffffffu, v, o);
        if (tid == 0) sc[1] = rsqrtf(v / (float)KVLORA + 1e-6f);
    }
    __syncthreads();

    float sq = sc[0], sk = sc[1];
    size_t qb = (size_t)t * QLORA;
    g_qln[qb + tid       ] = x0 * sq * qlnw[tid];
    g_qln[qb + tid + 512 ] = x1 * sq * qlnw[tid + 512];
    g_qln[qb + tid + 1024] = x2 * sq * qlnw[tid + 1024];
    out[OUT_KNOPE + (size_t)t * KVLORA + tid] = y * sk * kvlnw[tid];

    if (tid < 32) {
        float a = f[2048 + tid], b = f[2080 + tid];
        float c = g_cos[t * 32 + tid], sn = g_sin[t * 32 + tid];
        out[OUT_KPE + (size_t)t * 64 + tid     ] = a * c - b * sn;
        out[OUT_KPE + (size_t)t * 64 + 32 + tid] = b * c + a * sn;
    }
}

// ---------------- launch ----------------
extern "C" void kernel_launch(void* const* d_in, const int* in_sizes, int n_in,
                              void* d_out, int out_size)
{
    const int*   positions = (const int*)  d_in[0];
    const float* hidden    = (const float*)d_in[1];
    const float* w_fused   = (const float*)d_in[2];
    const float* q_ln_w    = (const float*)d_in[3];
    const float* w_qb      = (const float*)d_in[4];
    const float* kv_ln_w   = (const float*)d_in[5];
    const float* w_kc      = (const float*)d_in[6];
    float* out = (float*)d_out;

    // 1. rope table (fp64 trig, 131K threads)
    rope_table_kernel<<<(T_TOK * 32 + 255) / 256, 256>>>(positions);

    // 2. GEMM1: fused = hidden @ w_fused  -> g_fused
    gemm_tf32<0><<<32 * 17, 256>>>(hidden, 0, w_fused, nullptr, 1,
                                   T_TOK, FUSEDN, HID, HID, FUSEDN, FUSEDN,
                                   0, 0, 0);

    // 3. RMSNorms (+ k_nope, k_pe outputs, q_ln scratch)
    rms_split_kernel<<<T_TOK, 512>>>(q_ln_w, kv_ln_w, out);

    // 4. GEMM2: q = q_ln @ w_qb; epilogue splits nope->g_qnope and
    //    applies rope in-register, writing q_pe straight to out.
    gemm_tf32<1><<<32 * 192, 256>>>(nullptr, 2, w_qb, out + OUT_QPE, 0,
                                    T_TOK, NH * DQK, QLORA, QLORA, NH * DQK, 0,
                                    0, 0, 0);

    // 5. GEMM3 (batched over 128 heads): q_nope_out = q_nope @ w_kc[h]
    dim3 g3(32 * 4, 1, NH);
    gemm_tf32<0><<<g3, 256>>>(nullptr, 3, w_kc, out + OUT_QNOPE, 0,
                              T_TOK, KVLORA, DNOPE,
                              NH * DNOPE, KVLORA, NH * KVLORA,
                              /*bsA=*/DNOPE, /*bsB=*/(long long)DNOPE * KVLORA,
                              /*bsC=*/KVLORA);
}

// round 6
// speedup vs baseline: 1.2110x; 1.2110x over previous
#include <cuda_runtime.h>
#include <cstdint>
#include <cstddef>

// ---------------- problem constants ----------------
#define T_TOK   4096
#define HID     7168
#define NH      128
#define DNOPE   128
#define DROPE   64
#define QLORA   1536
#define KVLORA  512
#define DQK     192                 // DNOPE + DROPE
#define FUSEDN  2112                // QLORA + KVLORA + DROPE

// output layout (concat of q_pe, k_pe, q_nope_out, k_nope, all f32)
#define OUT_QPE    0
#define OUT_KPE    33554432LL       // T*H*64
#define OUT_QNOPE  33816576LL       // + T*64
#define OUT_KNOPE  302252032LL      // + T*H*512

// ---------------- device scratch (no allocations allowed) ----------------
__device__ float g_fused[(size_t)T_TOK * FUSEDN];          // 34.6 MB
__device__ float g_qln  [(size_t)T_TOK * QLORA];           // 25 MB
__device__ float g_qnope[(size_t)T_TOK * NH * DNOPE];      // 268 MB
__device__ float g_cos  [T_TOK * 32];
__device__ float g_sin  [T_TOK * 32];

// ---------------- helpers ----------------
__device__ __forceinline__ unsigned f2tf(float x) {
    unsigned r; asm("cvt.rna.tf32.f32 %0, %1;" : "=r"(r) : "f"(x)); return r;
}

__device__ __forceinline__ uint4 pack_tf32(float4 v) {
    uint4 p;
    p.x = f2tf(v.x); p.y = f2tf(v.y); p.z = f2tf(v.z); p.w = f2tf(v.w);
    return p;
}

__device__ __forceinline__ float* sel_ptr(int sel, const float* ext) {
    switch (sel) {
        case 1: return g_fused;
        case 2: return g_qln;
        case 3: return g_qnope;
        default: return (float*)ext;
    }
}

// ---------------- tf32 GEMM (double-buffered smem) ----------------
// C[M,N] = A[M,K] (row-major, lda) * B[K,N] (row-major, ldb)
// MODE 0: plain store to C (ldc).
// MODE 1: GEMM2 epilogue. Warp tiles are 64 cols wide; head h's rope region
//   [192h+128, 192h+192) is exactly one warp tile (192h+128 = 64*(3h+2)), so
//   a warp tile is either all-nope -> g_qnope, or all-rope -> rope applied
//   in-register (partners acc[..][ni] / acc[..][ni+4]) and stored to Cext
//   (= out + OUT_QPE).
//
// SMEM bank analysis (R3 ncu: L1=81% — crossbar bound):
//   sA row stride 20: af bank = grp*20+tig mod 32 -> 32 distinct (free)
//   sB row stride 136: bf bank = tig*8+grp mod 32 -> 32 distinct (free)
//   staging: STS.128 per float4 (rows 80B / 544B = 16B multiples; arrays
//   force-aligned 16B below so the wide stores are legal)
#define BM 128
#define BN 128
#define BK 16
#define SA_LD 20    // 80B rows
#define SB_LD 136   // 544B rows; 136 mod 32 == 8 -> conflict-free b-frags

template<int MODE>
__global__ __launch_bounds__(256)
void gemm_tf32(const float* __restrict__ Aext, int selA,
               const float* __restrict__ B,
               float* __restrict__ Cext, int selC,
               int M, int N, int K, int lda, int ldb, int ldc,
               long long bsA, long long bsB, long long bsC)
{
    __shared__ __align__(16) unsigned sA[2][BM][SA_LD];
    __shared__ __align__(16) unsigned sB[2][BK][SB_LD];

    const float* A = sel_ptr(selA, Aext);
    float*       C = sel_ptr(selC, Cext);
    A += (size_t)blockIdx.z * bsA;
    B += (size_t)blockIdx.z * bsB;
    C += (size_t)blockIdx.z * bsC;

    // grouped rasterization for L2 reuse
    const int tiles_n = (N + BN - 1) / BN;
    const int tiles_m = M / BM;
    const int GRP = 8;
    int pid   = blockIdx.x;
    int nig   = GRP * tiles_n;
    int gid   = pid / nig;
    int fm    = gid * GRP;
    int gsz   = min(GRP, tiles_m - fm);
    int tm    = fm + (pid % gsz);
    int tn    = (pid % nig) / gsz;
    int m0 = tm * BM, n0 = tn * BN;

    int tid  = threadIdx.x;
    int lane = tid & 31;
    int warp = tid >> 5;
    int wm   = warp & 3;        // 4 warps along M (32 rows each)
    int wn   = warp >> 2;       // 2 warps along N (64 cols each)
    int grp  = lane >> 2;       // 0..7
    int tig  = lane & 3;        // 0..3

    // per-thread global-load coordinates (fixed across K-tiles)
    int a_row0 = tid >> 2;
    int a_kc   = (tid & 3) << 2;
    int a_row1 = (tid + 256) >> 2;
    int b_kr0  = tid >> 5;
    int b_nc   = (tid & 31) << 2;
    int b_kr1  = (tid + 256) >> 5;
    bool bok   = (n0 + b_nc) < N;

    float acc[2][8][4];
    #pragma unroll
    for (int a = 0; a < 2; a++)
        #pragma unroll
        for (int b = 0; b < 8; b++)
            #pragma unroll
            for (int c = 0; c < 4; c++) acc[a][b][c] = 0.f;

    // ---- prologue: fetch K-tile 0, stage into smem buffer 0 ----
    float4 ra0, ra1, rb0, rb1;
    ra0 = *(const float4*)(A + (size_t)(m0 + a_row0) * lda + a_kc);
    ra1 = *(const float4*)(A + (size_t)(m0 + a_row1) * lda + a_kc);
    rb0 = make_float4(0.f, 0.f, 0.f, 0.f);
    rb1 = make_float4(0.f, 0.f, 0.f, 0.f);
    if (bok) {
        rb0 = *(const float4*)(B + (size_t)b_kr0 * ldb + n0 + b_nc);
        rb1 = *(const float4*)(B + (size_t)b_kr1 * ldb + n0 + b_nc);
    }
    *(uint4*)&sA[0][a_row0][a_kc] = pack_tf32(ra0);
    *(uint4*)&sA[0][a_row1][a_kc] = pack_tf32(ra1);
    *(uint4*)&sB[0][b_kr0][b_nc]  = pack_tf32(rb0);
    *(uint4*)&sB[0][b_kr1][b_nc]  = pack_tf32(rb1);
    __syncthreads();

    const int nk = K / BK;
    for (int it = 0; it < nk; it++) {
        int cur  = it & 1;
        int nxt  = cur ^ 1;
        int kn   = (it + 1) * BK;
        bool more = kn < K;

        // prefetch next K-tile into registers (overlaps MMA below)
        if (more) {
            ra0 = *(const float4*)(A + (size_t)(m0 + a_row0) * lda + kn + a_kc);
            ra1 = *(const float4*)(A + (size_t)(m0 + a_row1) * lda + kn + a_kc);
            if (bok) {
                rb0 = *(const float4*)(B + (size_t)(kn + b_kr0) * ldb + n0 + b_nc);
                rb1 = *(const float4*)(B + (size_t)(kn + b_kr1) * ldb + n0 + b_nc);
            }
        }

        // MMA on current buffer
        #pragma unroll
        for (int ks = 0; ks < BK; ks += 8) {
            unsigned af[2][4], bf[8][2];
            #pragma unroll
            for (int mi = 0; mi < 2; mi++) {
                int r = wm * 32 + mi * 16 + grp;
                af[mi][0] = sA[cur][r    ][ks + tig];
                af[mi][1] = sA[cur][r + 8][ks + tig];
                af[mi][2] = sA[cur][r    ][ks + tig + 4];
                af[mi][3] = sA[cur][r + 8][ks + tig + 4];
            }
            #pragma unroll
            for (int ni = 0; ni < 8; ni++) {
                int c = wn * 64 + ni * 8 + grp;
                bf[ni][0] = sB[cur][ks + tig    ][c];
                bf[ni][1] = sB[cur][ks + tig + 4][c];
            }
            #pragma unroll
            for (int mi = 0; mi < 2; mi++)
                #pragma unroll
                for (int ni = 0; ni < 8; ni++) {
                    asm volatile(
                        "mma.sync.aligned.m16n8k8.row.col.f32.tf32.tf32.f32 "
                        "{%0,%1,%2,%3}, {%4,%5,%6,%7}, {%8,%9}, {%0,%1,%2,%3};"
                        : "+f"(acc[mi][ni][0]), "+f"(acc[mi][ni][1]),
                          "+f"(acc[mi][ni][2]), "+f"(acc[mi][ni][3])
                        : "r"(af[mi][0]), "r"(af[mi][1]),
                          "r"(af[mi][2]), "r"(af[mi][3]),
                          "r"(bf[ni][0]), "r"(bf[ni][1]));
                }
        }

        // stage next tile into the other buffer (safe: that buffer's readers
        // finished before the barrier that ended the previous iteration)
        if (more) {
            *(uint4*)&sA[nxt][a_row0][a_kc] = pack_tf32(ra0);
            *(uint4*)&sA[nxt][a_row1][a_kc] = pack_tf32(ra1);
            *(uint4*)&sB[nxt][b_kr0][b_nc]  = pack_tf32(rb0);
            *(uint4*)&sB[nxt][b_kr1][b_nc]  = pack_tf32(rb1);
        }
        __syncthreads();
    }

    // ---------------- epilogue ----------------
    if (MODE == 0) {
        #pragma unroll
        for (int mi = 0; mi < 2; mi++)
            #pragma unroll
            for (int half = 0; half < 2; half++) {
                int row = m0 + wm * 32 + mi * 16 + grp + half * 8;
                #pragma unroll
                for (int ni = 0; ni < 8; ni++) {
                    int col = n0 + wn * 64 + ni * 8 + 2 * tig;
                    if (col >= N) continue;
                    *(float2*)(C + (size_t)row * ldc + col)
                        = make_float2(acc[mi][ni][half * 2 + 0],
                                      acc[mi][ni][half * 2 + 1]);
                }
            }
    } else {
        int wbase   = n0 + wn * 64;              // warp-tile column base
        bool isrope = ((wbase >> 6) % 3) == 2;   // 64-col block idx mod 3
        if (!isrope) {
            #pragma unroll
            for (int mi = 0; mi < 2; mi++)
                #pragma unroll
                for (int half = 0; half < 2; half++) {
                    int row = m0 + wm * 32 + mi * 16 + grp + half * 8;
                    #pragma unroll
                    for (int ni = 0; ni < 8; ni++) {
                        int col  = wbase + ni * 8 + 2 * tig;
                        int head = col / DQK;
                        int w    = col - head * DQK;     // < 128 guaranteed
                        *(float2*)(g_qnope + (size_t)row * (NH * DNOPE)
                                   + head * DNOPE + w)
                            = make_float2(acc[mi][ni][half * 2 + 0],
                                          acc[mi][ni][half * 2 + 1]);
                    }
                }
        } else {
            int head = wbase / DQK;              // whole warp tile = one head's rope
            #pragma unroll
            for (int mi = 0; mi < 2; mi++)
                #pragma unroll
                for (int half = 0; half < 2; half++) {
                    int row = m0 + wm * 32 + mi * 16 + grp + half * 8;  // token t
                    float* ob = C + (size_t)row * (NH * DROPE) + head * DROPE;
                    const float* cp = g_cos + row * 32;
                    const float* sp = g_sin + row * 32;
                    #pragma unroll
                    for (int ni = 0; ni < 4; ni++) {
                        int j  = ni * 8 + 2 * tig;       // 0..30 (pairs j, j+1)
                        float a0 = acc[mi][ni    ][half * 2 + 0];
                        float a1 = acc[mi][ni    ][half * 2 + 1];
                        float b0 = acc[mi][ni + 4][half * 2 + 0];
                        float b1 = acc[mi][ni + 4][half * 2 + 1];
                        float c0 = cp[j], c1 = cp[j + 1];
                        float s0 = sp[j], s1 = sp[j + 1];
                        *(float2*)(ob + j)      = make_float2(a0 * c0 - b0 * s0,
                                                              a1 * c1 - b1 * s1);
                        *(float2*)(ob + 32 + j) = make_float2(b0 * c0 + a0 * s0,
                                                              b1 * c1 + a1 * s1);
                    }
                }
        }
    }
}

// ---------------- rope table (fp64 trig once per (t, j)) ----------------
__global__ void rope_table_kernel(const int* __restrict__ pos) {
    int idx = blockIdx.x * blockDim.x + threadIdx.x;
    if (idx >= T_TOK * 32) return;
    int t = idx >> 5, j = idx & 31;
    double inv = exp(-(double)j * (9.210340371976184 / 32.0));  // ln(1e4)/32
    double ang = (double)pos[t] * inv;
    g_cos[idx] = (float)cos(ang);
    g_sin[idx] = (float)sin(ang);
}

// ---------------- per-token: both RMSNorms + k_pe rope ----------------
__global__ __launch_bounds__(512)
void rms_split_kernel(const float* __restrict__ qlnw,
                      const float* __restrict__ kvlnw,
                      float* __restrict__ out)
{
    int t = blockIdx.x;
    const float* f = g_fused + (size_t)t * FUSEDN;
    int tid = threadIdx.x;
    __shared__ float red[16];
    __shared__ float sc[2];

    float x0 = f[tid], x1 = f[tid + 512], x2 = f[tid + 1024];
    float s = x0 * x0 + x1 * x1 + x2 * x2;
    #pragma unroll
    for (int o = 16; o; o >>= 1) s += __shfl_xor_sync(0xffffffffu, s, o);
    if ((tid & 31) == 0) red[tid >> 5] = s;
    __syncthreads();
    if (tid < 32) {
        float v = (tid < 16) ? red[tid] : 0.f;
        #pragma unroll
        for (int o = 8; o; o >>= 1) v += __shfl_xor_sync(0xffffffffu, v, o);
        if (tid == 0) sc[0] = rsqrtf(v / (float)QLORA + 1e-6f);
    }
    __syncthreads();

    float y  = f[1536 + tid];
    float s2 = y * y;
    #pragma unroll
    for (int o = 16; o; o >>= 1) s2 += __shfl_xor_sync(0xffffffffu, s2, o);
    if ((tid & 31) == 0) red[tid >> 5] = s2;
    __syncthreads();
    if (tid < 32) {
        float v = (tid < 16) ? red[tid] : 0.f;
        #pragma unroll
        for (int o = 8; o; o >>= 1) v += __shfl_xor_sync(0xffffffffu, v, o);
        if (tid == 0) sc[1] = rsqrtf(v / (float)KVLORA + 1e-6f);
    }
    __syncthreads();

    float sq = sc[0], sk = sc[1];
    size_t qb = (size_t)t * QLORA;
    g_qln[qb + tid       ] = x0 * sq * qlnw[tid];
    g_qln[qb + tid + 512 ] = x1 * sq * qlnw[tid + 512];
    g_qln[qb + tid + 1024] = x2 * sq * qlnw[tid + 1024];
    out[OUT_KNOPE + (size_t)t * KVLORA + tid] = y * sk * kvlnw[tid];

    if (tid < 32) {
        float a = f[2048 + tid], b = f[2080 + tid];
        float c = g_cos[t * 32 + tid], sn = g_sin[t * 32 + tid];
        out[OUT_KPE + (size_t)t * 64 + tid     ] = a * c - b * sn;
        out[OUT_KPE + (size_t)t * 64 + 32 + tid] = b * c + a * sn;
    }
}

// ---------------- launch ----------------
extern "C" void kernel_launch(void* const* d_in, const int* in_sizes, int n_in,
                              void* d_out, int out_size)
{
    const int*   positions = (const int*)  d_in[0];
    const float* hidden    = (const float*)d_in[1];
    const float* w_fused   = (const float*)d_in[2];
    const float* q_ln_w    = (const float*)d_in[3];
    const float* w_qb      = (const float*)d_in[4];
    const float* kv_ln_w   = (const float*)d_in[5];
    const float* w_kc      = (const float*)d_in[6];
    float* out = (float*)d_out;

    // 1. rope table (fp64 trig, 131K threads)
    rope_table_kernel<<<(T_TOK * 32 + 255) / 256, 256>>>(positions);

    // 2. GEMM1: fused = hidden @ w_fused  -> g_fused
    gemm_tf32<0><<<32 * 17, 256>>>(hidden, 0, w_fused, nullptr, 1,
                                   T_TOK, FUSEDN, HID, HID, FUSEDN, FUSEDN,
                                   0, 0, 0);

    // 3. RMSNorms (+ k_nope, k_pe outputs, q_ln scratch)
    rms_split_kernel<<<T_TOK, 512>>>(q_ln_w, kv_ln_w, out);

    // 4. GEMM2: q = q_ln @ w_qb; epilogue splits nope->g_qnope and
    //    applies rope in-register, writing q_pe straight to out.
    gemm_tf32<1><<<32 * 192, 256>>>(nullptr, 2, w_qb, out + OUT_QPE, 0,
                                    T_TOK, NH * DQK, QLORA, QLORA, NH * DQK, 0,
                                    0, 0, 0);

    // 5. GEMM3 (batched over 128 heads): q_nope_out = q_nope @ w_kc[h]
    dim3 g3(32 * 4, 1, NH);
    gemm_tf32<0><<<g3, 256>>>(nullptr, 3, w_kc, out + OUT_QNOPE, 0,
                              T_TOK, KVLORA, DNOPE,
                              NH * DNOPE, KVLORA, NH * KVLORA,
                              /*bsA=*/DNOPE, /*bsB=*/(long long)DNOPE * KVLORA,
                              /*bsC=*/KVLORA);
}